// round 1
// baseline (speedup 1.0000x reference)
#include <cuda_runtime.h>
#include <math_constants.h>

#define BATCH 4
#define SEQ   4096
#define DM    512
#define MTOT  (BATCH*SEQ)

// GEMM tiling
#define BM 128
#define BN 128
#define BK 16
#define TM 8
#define TN 8
#define PAD 4
#define LDA (BM+PAD)
#define LDB (BN+PAD)

// Scratch for Q, K, V projections (96 MB total) — static __device__ arrays
// are the allowed scratch mechanism (no cudaMalloc permitted).
__device__ float g_Q[(size_t)MTOT*DM];
__device__ float g_K[(size_t)MTOT*DM];
__device__ float g_V[(size_t)MTOT*DM];

// ---------------------------------------------------------------------------
// Kernel 1: QKV projection.  C[m,e] = sum_d x[m,d] * W[e,d]   (NT layout)
// blockIdx.z selects which of {Q,K,V} this block computes.
// ---------------------------------------------------------------------------
__global__ __launch_bounds__(256) void qkv_kernel(
    const float* __restrict__ x,
    const float* __restrict__ Wq,
    const float* __restrict__ Wk,
    const float* __restrict__ Wv)
{
    __shared__ float As[BK*LDA];
    __shared__ float Bs[BK*LDB];

    const float* W;
    float* C;
    if (blockIdx.z == 0)      { W = Wq; C = g_Q; }
    else if (blockIdx.z == 1) { W = Wk; C = g_K; }
    else                      { W = Wv; C = g_V; }

    const int m0  = blockIdx.y * BM;
    const int n0  = blockIdx.x * BN;
    const int tid = threadIdx.x;
    const int tx  = tid & 15;
    const int ty  = tid >> 4;

    float acc[TM][TN];
#pragma unroll
    for (int i = 0; i < TM; i++)
#pragma unroll
        for (int j = 0; j < TN; j++) acc[i][j] = 0.f;

    for (int k0 = 0; k0 < DM; k0 += BK) {
        // Load A tile (x): rows m0..m0+127, cols k0..k0+15, transpose to As[k][m]
        // Load B tile (W): rows n0..n0+127, cols k0..k0+15, transpose to Bs[k][n]
#pragma unroll
        for (int l = 0; l < 2; l++) {
            int v   = tid + l*256;        // 512 float4 per tile
            int row = v >> 2;             // 4 float4 per row (BK=16)
            int c4  = (v & 3) << 2;
            float4 a = *reinterpret_cast<const float4*>(
                &x[(size_t)(m0+row)*DM + k0 + c4]);
            As[(c4+0)*LDA + row] = a.x;
            As[(c4+1)*LDA + row] = a.y;
            As[(c4+2)*LDA + row] = a.z;
            As[(c4+3)*LDA + row] = a.w;
            float4 b = *reinterpret_cast<const float4*>(
                &W[(size_t)(n0+row)*DM + k0 + c4]);
            Bs[(c4+0)*LDB + row] = b.x;
            Bs[(c4+1)*LDB + row] = b.y;
            Bs[(c4+2)*LDB + row] = b.z;
            Bs[(c4+3)*LDB + row] = b.w;
        }
        __syncthreads();

#pragma unroll
        for (int k = 0; k < BK; k++) {
            float4 a0 = *reinterpret_cast<const float4*>(&As[k*LDA + ty*TM]);
            float4 a1 = *reinterpret_cast<const float4*>(&As[k*LDA + ty*TM + 4]);
            float4 b0 = *reinterpret_cast<const float4*>(&Bs[k*LDB + tx*TN]);
            float4 b1 = *reinterpret_cast<const float4*>(&Bs[k*LDB + tx*TN + 4]);
            float ra[TM] = {a0.x,a0.y,a0.z,a0.w,a1.x,a1.y,a1.z,a1.w};
            float rb[TN] = {b0.x,b0.y,b0.z,b0.w,b1.x,b1.y,b1.z,b1.w};
#pragma unroll
            for (int i = 0; i < TM; i++)
#pragma unroll
                for (int j = 0; j < TN; j++)
                    acc[i][j] = fmaf(ra[i], rb[j], acc[i][j]);
        }
        __syncthreads();
    }

#pragma unroll
    for (int i = 0; i < TM; i++) {
        size_t rowoff = (size_t)(m0 + ty*TM + i)*DM + n0 + tx*TN;
#pragma unroll
        for (int j = 0; j < TN; j += 4) {
            float4 o = make_float4(acc[i][j], acc[i][j+1], acc[i][j+2], acc[i][j+3]);
            *reinterpret_cast<float4*>(&C[rowoff + j]) = o;
        }
    }
}

// ---------------------------------------------------------------------------
// Kernel 2: causal scores.  S[q,k] = (Q[q,:] . K[k,:]) / sqrt(D), k<=q else 0
// ---------------------------------------------------------------------------
__global__ __launch_bounds__(256) void scores_kernel(float* __restrict__ attn)
{
    const int b  = blockIdx.z;
    const int m0 = blockIdx.y * BM;   // query rows
    const int n0 = blockIdx.x * BN;   // key cols
    float* C = attn + (size_t)b*SEQ*SEQ;
    const int tid = threadIdx.x;

    if (n0 > m0 + BM - 1) {
        // Tile fully above diagonal: write zeros (coalesced float4) and exit.
        for (int i = tid; i < BM*BN/4; i += 256) {
            int row = i >> 5;            // 32 float4 per 128-wide row
            int c   = (i & 31) << 2;
            *reinterpret_cast<float4*>(&C[(size_t)(m0+row)*SEQ + n0 + c]) =
                make_float4(0.f, 0.f, 0.f, 0.f);
        }
        return;
    }

    __shared__ float As[BK*LDA];
    __shared__ float Bs[BK*LDB];
    const float* A  = g_Q + (size_t)b*SEQ*DM;
    const float* Bm = g_K + (size_t)b*SEQ*DM;
    const int tx = tid & 15;
    const int ty = tid >> 4;

    float acc[TM][TN];
#pragma unroll
    for (int i = 0; i < TM; i++)
#pragma unroll
        for (int j = 0; j < TN; j++) acc[i][j] = 0.f;

    for (int k0 = 0; k0 < DM; k0 += BK) {
#pragma unroll
        for (int l = 0; l < 2; l++) {
            int v   = tid + l*256;
            int row = v >> 2;
            int c4  = (v & 3) << 2;
            float4 a = *reinterpret_cast<const float4*>(
                &A[(size_t)(m0+row)*DM + k0 + c4]);
            As[(c4+0)*LDA + row] = a.x;
            As[(c4+1)*LDA + row] = a.y;
            As[(c4+2)*LDA + row] = a.z;
            As[(c4+3)*LDA + row] = a.w;
            float4 bb = *reinterpret_cast<const float4*>(
                &Bm[(size_t)(n0+row)*DM + k0 + c4]);
            Bs[(c4+0)*LDB + row] = bb.x;
            Bs[(c4+1)*LDB + row] = bb.y;
            Bs[(c4+2)*LDB + row] = bb.z;
            Bs[(c4+3)*LDB + row] = bb.w;
        }
        __syncthreads();

#pragma unroll
        for (int k = 0; k < BK; k++) {
            float4 a0 = *reinterpret_cast<const float4*>(&As[k*LDA + ty*TM]);
            float4 a1 = *reinterpret_cast<const float4*>(&As[k*LDA + ty*TM + 4]);
            float4 b0 = *reinterpret_cast<const float4*>(&Bs[k*LDB + tx*TN]);
            float4 b1 = *reinterpret_cast<const float4*>(&Bs[k*LDB + tx*TN + 4]);
            float ra[TM] = {a0.x,a0.y,a0.z,a0.w,a1.x,a1.y,a1.z,a1.w};
            float rb[TN] = {b0.x,b0.y,b0.z,b0.w,b1.x,b1.y,b1.z,b1.w};
#pragma unroll
            for (int i = 0; i < TM; i++)
#pragma unroll
                for (int j = 0; j < TN; j++)
                    acc[i][j] = fmaf(ra[i], rb[j], acc[i][j]);
        }
        __syncthreads();
    }

    const float alpha = 0.044194173824159216f;   // 1/sqrt(512)
#pragma unroll
    for (int i = 0; i < TM; i++) {
        int q = m0 + ty*TM + i;
#pragma unroll
        for (int j = 0; j < TN; j++) {
            int kk = n0 + tx*TN + j;
            C[(size_t)q*SEQ + kk] = (kk <= q) ? acc[i][j]*alpha : 0.f;
        }
    }
}

// ---------------------------------------------------------------------------
// Kernel 3: in-place causal row softmax.  One block per (b, q) row.
// ---------------------------------------------------------------------------
__global__ __launch_bounds__(256) void softmax_kernel(float* __restrict__ attn)
{
    const int r = blockIdx.x;
    const int b = r / SEQ;
    const int q = r % SEQ;
    float* row  = attn + (size_t)b*SEQ*SEQ + (size_t)q*SEQ;
    const int n = q + 1;
    const int tid = threadIdx.x;

    float v[16];
    float mx = -CUDART_INF_F;
    for (int i = tid, j = 0; i < n; i += 256, j++) {
        v[j] = row[i];
        mx = fmaxf(mx, v[j]);
    }

    __shared__ float red[256];
    red[tid] = mx;
    __syncthreads();
    for (int s = 128; s > 0; s >>= 1) {
        if (tid < s) red[tid] = fmaxf(red[tid], red[tid+s]);
        __syncthreads();
    }
    mx = red[0];
    __syncthreads();

    float sum = 0.f;
    for (int i = tid, j = 0; i < n; i += 256, j++) {
        v[j] = __expf(v[j] - mx);
        sum += v[j];
    }
    red[tid] = sum;
    __syncthreads();
    for (int s = 128; s > 0; s >>= 1) {
        if (tid < s) red[tid] += red[tid+s];
        __syncthreads();
    }
    const float inv = 1.0f / red[0];

    for (int i = tid, j = 0; i < n; i += 256, j++)
        row[i] = v[j] * inv;
}

// ---------------------------------------------------------------------------
// Kernel 4: out = x + P @ V   (NN layout; causal K-limit k < m0+BM)
// ---------------------------------------------------------------------------
__global__ __launch_bounds__(256) void av_kernel(
    const float* __restrict__ x,
    const float* __restrict__ attn,
    float* __restrict__ out)
{
    __shared__ float As[BK*LDA];
    __shared__ float Bs[BK*LDB];

    const int b  = blockIdx.z;
    const int m0 = blockIdx.y * BM;   // query rows
    const int n0 = blockIdx.x * BN;   // model-dim cols
    const float* A = attn + (size_t)b*SEQ*SEQ;
    const float* V = g_V  + (size_t)b*SEQ*DM;
    const int tid = threadIdx.x;
    const int tx  = tid & 15;
    const int ty  = tid >> 4;

    float acc[TM][TN];
#pragma unroll
    for (int i = 0; i < TM; i++)
#pragma unroll
        for (int j = 0; j < TN; j++) acc[i][j] = 0.f;

    const int kmax = m0 + BM;   // rows in this tile attend only to k <= m0+127

    for (int k0 = 0; k0 < kmax; k0 += BK) {
        // A tile: attn rows m0..+127, cols k0..+15 (stride SEQ), transpose
#pragma unroll
        for (int l = 0; l < 2; l++) {
            int v   = tid + l*256;
            int row = v >> 2;
            int c4  = (v & 3) << 2;
            float4 a = *reinterpret_cast<const float4*>(
                &A[(size_t)(m0+row)*SEQ + k0 + c4]);
            As[(c4+0)*LDA + row] = a.x;
            As[(c4+1)*LDA + row] = a.y;
            As[(c4+2)*LDA + row] = a.z;
            As[(c4+3)*LDA + row] = a.w;
        }
        // B tile: V rows k0..+15, cols n0..+127 (stride DM), direct layout
#pragma unroll
        for (int l = 0; l < 2; l++) {
            int v   = tid + l*256;
            int row = v >> 5;            // 32 float4 per 128-wide row
            int c4  = (v & 31) << 2;
            float4 bb = *reinterpret_cast<const float4*>(
                &V[(size_t)(k0+row)*DM + n0 + c4]);
            *reinterpret_cast<float4*>(&Bs[row*LDB + c4]) = bb;
        }
        __syncthreads();

#pragma unroll
        for (int k = 0; k < BK; k++) {
            float4 a0 = *reinterpret_cast<const float4*>(&As[k*LDA + ty*TM]);
            float4 a1 = *reinterpret_cast<const float4*>(&As[k*LDA + ty*TM + 4]);
            float4 b0 = *reinterpret_cast<const float4*>(&Bs[k*LDB + tx*TN]);
            float4 b1 = *reinterpret_cast<const float4*>(&Bs[k*LDB + tx*TN + 4]);
            float ra[TM] = {a0.x,a0.y,a0.z,a0.w,a1.x,a1.y,a1.z,a1.w};
            float rb[TN] = {b0.x,b0.y,b0.z,b0.w,b1.x,b1.y,b1.z,b1.w};
#pragma unroll
            for (int i = 0; i < TM; i++)
#pragma unroll
                for (int j = 0; j < TN; j++)
                    acc[i][j] = fmaf(ra[i], rb[j], acc[i][j]);
        }
        __syncthreads();
    }

    // Epilogue: out = x + P@V
#pragma unroll
    for (int i = 0; i < TM; i++) {
        size_t gm = (size_t)b*SEQ + m0 + ty*TM + i;
        size_t off = gm*DM + n0 + tx*TN;
#pragma unroll
        for (int j = 0; j < TN; j += 4) {
            float4 xr = *reinterpret_cast<const float4*>(&x[off + j]);
            float4 o  = make_float4(acc[i][j]   + xr.x,
                                    acc[i][j+1] + xr.y,
                                    acc[i][j+2] + xr.z,
                                    acc[i][j+3] + xr.w);
            *reinterpret_cast<float4*>(&out[off + j]) = o;
        }
    }
}

// ---------------------------------------------------------------------------
extern "C" void kernel_launch(void* const* d_in, const int* in_sizes, int n_in,
                              void* d_out, int out_size)
{
    const float* x  = (const float*)d_in[0];
    const float* Wq = (const float*)d_in[1];
    const float* Wk = (const float*)d_in[2];
    const float* Wv = (const float*)d_in[3];

    float* out  = (float*)d_out;                       // [B*S, D]
    float* attn = out + (size_t)BATCH*SEQ*DM;          // [B, S, S]

    dim3 t(256);
    qkv_kernel   <<<dim3(DM/BN,  MTOT/BM, 3),     t>>>(x, Wq, Wk, Wv);
    scores_kernel<<<dim3(SEQ/BN, SEQ/BM,  BATCH), t>>>(attn);
    softmax_kernel<<<MTOT, t>>>(attn);
    av_kernel    <<<dim3(DM/BN,  SEQ/BM,  BATCH), t>>>(x, attn, out);
}

// round 5
// speedup vs baseline: 2.2213x; 2.2213x over previous
#include <cuda_runtime.h>
#include <cuda_bf16.h>
#include <math_constants.h>
#include <cstdint>

#define BATCH 4
#define SEQ   4096
#define DM    512
#define MTOT  (BATCH*SEQ)

// CTA tile 128x128, K-chunk 32 (bf16 elements). 8 warps: 4 (m) x 2 (n).
// Warp tile: 32 (m) x 64 (n). mma.m16n8k16 bf16, 3-product hi/lo split.
#define BM 128
#define BN 128
#define BK 32
#define SROW 20          // smem row stride in uint32 (40 bf16 = 80 bytes)

// ---------------------------------------------------------------------------
// Scratch (static __device__ arrays = sanctioned scratch)
// ---------------------------------------------------------------------------
__device__ float g_Q [(size_t)MTOT*DM];
__device__ float g_K [(size_t)MTOT*DM];
__device__ float g_Vt[(size_t)BATCH*DM*SEQ];    // V transposed: [b][d][s]

// ---------------------------------------------------------------------------
__device__ __forceinline__ uint32_t smem_u32(const void* p) {
    uint32_t a;
    asm("{ .reg .u64 t; cvta.to.shared.u64 t, %1; cvt.u32.u64 %0, t; }" : "=r"(a) : "l"(p));
    return a;
}

__device__ __forceinline__ void split2(float x, float y, uint32_t& hi, uint32_t& lo) {
    __nv_bfloat16 hx = __float2bfloat16_rn(x);
    __nv_bfloat16 hy = __float2bfloat16_rn(y);
    __nv_bfloat16 lx = __float2bfloat16_rn(x - __bfloat162float(hx));
    __nv_bfloat16 ly = __float2bfloat16_rn(y - __bfloat162float(hy));
    hi = ((uint32_t)__bfloat16_as_ushort(hy) << 16) | __bfloat16_as_ushort(hx);
    lo = ((uint32_t)__bfloat16_as_ushort(ly) << 16) | __bfloat16_as_ushort(lx);
}

__device__ __forceinline__ void ldmx4(uint32_t* r, uint32_t addr) {
    asm volatile("ldmatrix.sync.aligned.m8n8.x4.shared.b16 {%0,%1,%2,%3}, [%4];"
                 : "=r"(r[0]), "=r"(r[1]), "=r"(r[2]), "=r"(r[3]) : "r"(addr));
}

__device__ __forceinline__ void mma16816(float* c, const uint32_t* a, uint32_t b0, uint32_t b1) {
    asm volatile("mma.sync.aligned.m16n8k16.row.col.f32.bf16.bf16.f32 "
                 "{%0,%1,%2,%3}, {%4,%5,%6,%7}, {%8,%9}, {%0,%1,%2,%3};"
                 : "+f"(c[0]), "+f"(c[1]), "+f"(c[2]), "+f"(c[3])
                 : "r"(a[0]), "r"(a[1]), "r"(a[2]), "r"(a[3]), "r"(b0), "r"(b1));
}

// ---------------------------------------------------------------------------
// Shared-memory tiles (static: 40 KB total)
// ---------------------------------------------------------------------------
struct SmemTiles {
    uint32_t Ah[BM * SROW];
    uint32_t Al[BM * SROW];
    uint32_t Bh[BN * SROW];
    uint32_t Bl[BN * SROW];
};

// Load one 128x32 fp32 tile, split into hi/lo bf16, store to smem.
__device__ __forceinline__ void load_tile_split(
    const float* __restrict__ g, size_t ld, int k0,
    uint32_t* __restrict__ sHi, uint32_t* __restrict__ sLo, int tid)
{
#pragma unroll
    for (int t = 0; t < 4; t++) {
        int idx = tid + t * 256;
        int row = idx >> 3;
        int f4  = idx & 7;
        float4 v = *reinterpret_cast<const float4*>(g + (size_t)row * ld + k0 + f4 * 4);
        uint32_t h0, l0, h1, l1;
        split2(v.x, v.y, h0, l0);
        split2(v.z, v.w, h1, l1);
        uint32_t off = row * SROW + f4 * 2;
        *reinterpret_cast<uint2*>(sHi + off) = make_uint2(h0, h1);
        *reinterpret_cast<uint2*>(sLo + off) = make_uint2(l0, l1);
    }
}

// ---------------------------------------------------------------------------
// Mainloop: accumulate C[128,128] over nchunks K-chunks of 32.
// acc layout: [mtile 0..1][ntile 0..7][reg 0..3]
// B fragments are loaded inside the np loop to cap live registers (~104).
// ---------------------------------------------------------------------------
__device__ __forceinline__ void mma_mainloop(
    const float* __restrict__ At, size_t lda,
    const float* __restrict__ Bt, size_t ldb,
    int nchunks, SmemTiles* sm, float acc[2][8][4], int tid)
{
    const int lid = tid & 31;
    const int wid = tid >> 5;
    const int wm  = wid & 3;            // 0..3
    const int wn  = wid >> 2;           // 0..1

    const uint32_t sAh = smem_u32(sm->Ah);
    const uint32_t sAl = smem_u32(sm->Al);
    const uint32_t sBh = smem_u32(sm->Bh);
    const uint32_t sBl = smem_u32(sm->Bl);

    // ldmatrix lane addressing: row = base + (lid & 15); k-half via (lid >> 4)
    const uint32_t lrow = (lid & 15);
    const uint32_t lkof = (lid >> 4) * 16;   // bytes

    for (int c = 0; c < nchunks; c++) {
        const int k0 = c * BK;
        load_tile_split(At, lda, k0, sm->Ah, sm->Al, tid);
        load_tile_split(Bt, ldb, k0, sm->Bh, sm->Bl, tid);
        __syncthreads();

#pragma unroll
        for (int ks = 0; ks < 2; ks++) {
            const uint32_t kb = ks * 32 + lkof;       // byte offset in row
            uint32_t a_hi[2][4], a_lo[2][4];
#pragma unroll
            for (int mt = 0; mt < 2; mt++) {
                uint32_t ro = (wm * 32 + mt * 16 + lrow) * 80 + kb;
                ldmx4(a_hi[mt], sAh + ro);
                ldmx4(a_lo[mt], sAl + ro);
            }
#pragma unroll
            for (int np = 0; np < 4; np++) {
                uint32_t ro = (wn * 64 + np * 16 + lrow) * 80 + kb;
                uint32_t b_hi[4], b_lo[4];
                ldmx4(b_hi, sBh + ro);
                ldmx4(b_lo, sBl + ro);
#pragma unroll
                for (int mt = 0; mt < 2; mt++)
#pragma unroll
                    for (int h = 0; h < 2; h++) {
                        float* cc = acc[mt][np * 2 + h];
                        mma16816(cc, a_hi[mt], b_hi[h], b_hi[h + 2]);
                        mma16816(cc, a_hi[mt], b_lo[h], b_lo[h + 2]);
                        mma16816(cc, a_lo[mt], b_hi[h], b_hi[h + 2]);
                    }
            }
        }
        __syncthreads();
    }
}

// Epilogue coordinate helper: for (mt, nt), thread writes
//   (row0, col0) = value pair {c0,c1}, (row0+8, col0) = {c2,c3}
// row0 = wm*32 + mt*16 + (lid>>2), col0 = wn*64 + nt*8 + (lid&3)*2

// ---------------------------------------------------------------------------
// Kernel 1: QKV projection.  C[m,e] = sum_d x[m,d] * W[e,d]
// ---------------------------------------------------------------------------
__global__ __launch_bounds__(256, 2) void qkv_mma(
    const float* __restrict__ x,
    const float* __restrict__ Wq,
    const float* __restrict__ Wk,
    const float* __restrict__ Wv)
{
    __shared__ SmemTiles sm;
    const int tid = threadIdx.x, lid = tid & 31, wid = tid >> 5;
    const int wm = wid & 3, wn = wid >> 2;
    const int z  = blockIdx.z;
    const int m0 = blockIdx.y * BM;
    const int n0 = blockIdx.x * BN;
    const float* W = (z == 0) ? Wq : (z == 1) ? Wk : Wv;

    float acc[2][8][4];
#pragma unroll
    for (int a = 0; a < 2; a++)
#pragma unroll
        for (int b = 0; b < 8; b++)
#pragma unroll
            for (int r = 0; r < 4; r++) acc[a][b][r] = 0.f;

    mma_mainloop(x + (size_t)m0 * DM, DM, W + (size_t)n0 * DM, DM,
                 DM / BK, &sm, acc, tid);

    if (z < 2) {
        float* C = (z == 0) ? g_Q : g_K;
#pragma unroll
        for (int mt = 0; mt < 2; mt++) {
            int row0 = m0 + wm * 32 + mt * 16 + (lid >> 2);
#pragma unroll
            for (int nt = 0; nt < 8; nt++) {
                int col0 = n0 + wn * 64 + nt * 8 + (lid & 3) * 2;
                *reinterpret_cast<float2*>(C + (size_t)row0 * DM + col0) =
                    make_float2(acc[mt][nt][0], acc[mt][nt][1]);
                *reinterpret_cast<float2*>(C + (size_t)(row0 + 8) * DM + col0) =
                    make_float2(acc[mt][nt][2], acc[mt][nt][3]);
            }
        }
    } else {
        // V transposed: g_Vt[b][d][s], d = col, s = row & 4095
#pragma unroll
        for (int mt = 0; mt < 2; mt++) {
            int row0 = m0 + wm * 32 + mt * 16 + (lid >> 2);
            int b0 = row0 >> 12, s0 = row0 & (SEQ - 1);
            int b1 = (row0 + 8) >> 12, s1 = (row0 + 8) & (SEQ - 1);
#pragma unroll
            for (int nt = 0; nt < 8; nt++) {
                int col0 = n0 + wn * 64 + nt * 8 + (lid & 3) * 2;
                g_Vt[((size_t)b0 * DM + col0)     * SEQ + s0] = acc[mt][nt][0];
                g_Vt[((size_t)b0 * DM + col0 + 1) * SEQ + s0] = acc[mt][nt][1];
                g_Vt[((size_t)b1 * DM + col0)     * SEQ + s1] = acc[mt][nt][2];
                g_Vt[((size_t)b1 * DM + col0 + 1) * SEQ + s1] = acc[mt][nt][3];
            }
        }
    }
}

// ---------------------------------------------------------------------------
// Kernel 2: causal scores.  attn[q,k] = (Q[q]·K[k])/sqrt(D) for k<=q else 0
// ---------------------------------------------------------------------------
__global__ __launch_bounds__(256, 2) void scores_mma(float* __restrict__ attn)
{
    const int tid = threadIdx.x, lid = tid & 31, wid = tid >> 5;
    const int wm = wid & 3, wn = wid >> 2;
    const int b  = blockIdx.z;
    const int m0 = blockIdx.y * BM;
    const int n0 = blockIdx.x * BN;
    float* C = attn + (size_t)b * SEQ * SEQ;

    if (n0 > m0) {   // fully above diagonal: zero-fill
        for (int i = tid; i < BM * BN / 4; i += 256) {
            int row = i >> 5;
            int cc  = (i & 31) << 2;
            *reinterpret_cast<float4*>(&C[(size_t)(m0 + row) * SEQ + n0 + cc]) =
                make_float4(0.f, 0.f, 0.f, 0.f);
        }
        return;
    }

    __shared__ SmemTiles sm;
    float acc[2][8][4];
#pragma unroll
    for (int a = 0; a < 2; a++)
#pragma unroll
        for (int bb = 0; bb < 8; bb++)
#pragma unroll
            for (int r = 0; r < 4; r++) acc[a][bb][r] = 0.f;

    const float* Qb = g_Q + (size_t)b * SEQ * DM;
    const float* Kb = g_K + (size_t)b * SEQ * DM;
    mma_mainloop(Qb + (size_t)m0 * DM, DM, Kb + (size_t)n0 * DM, DM,
                 DM / BK, &sm, acc, tid);

    const float alpha = 0.044194173824159216f;   // 1/sqrt(512)
#pragma unroll
    for (int mt = 0; mt < 2; mt++) {
        int row0 = m0 + wm * 32 + mt * 16 + (lid >> 2);
        int row1 = row0 + 8;
#pragma unroll
        for (int nt = 0; nt < 8; nt++) {
            int col0 = n0 + wn * 64 + nt * 8 + (lid & 3) * 2;
            float2 v0, v1;
            v0.x = (col0     <= row0) ? acc[mt][nt][0] * alpha : 0.f;
            v0.y = (col0 + 1 <= row0) ? acc[mt][nt][1] * alpha : 0.f;
            v1.x = (col0     <= row1) ? acc[mt][nt][2] * alpha : 0.f;
            v1.y = (col0 + 1 <= row1) ? acc[mt][nt][3] * alpha : 0.f;
            *reinterpret_cast<float2*>(C + (size_t)row0 * SEQ + col0) = v0;
            *reinterpret_cast<float2*>(C + (size_t)row1 * SEQ + col0) = v1;
        }
    }
}

// ---------------------------------------------------------------------------
// Kernel 3: in-place causal row softmax (one block per (b,q) row)
// ---------------------------------------------------------------------------
__global__ __launch_bounds__(256) void softmax_kernel(float* __restrict__ attn)
{
    const int r = blockIdx.x;
    const int b = r / SEQ;
    const int q = r % SEQ;
    float* row  = attn + (size_t)b * SEQ * SEQ + (size_t)q * SEQ;
    const int n = q + 1;
    const int tid = threadIdx.x;

    float v[16];
    float mx = -CUDART_INF_F;
    for (int i = tid, j = 0; i < n; i += 256, j++) { v[j] = row[i]; mx = fmaxf(mx, v[j]); }

    __shared__ float red[256];
    red[tid] = mx;
    __syncthreads();
    for (int s = 128; s > 0; s >>= 1) {
        if (tid < s) red[tid] = fmaxf(red[tid], red[tid + s]);
        __syncthreads();
    }
    mx = red[0];
    __syncthreads();

    float sum = 0.f;
    for (int i = tid, j = 0; i < n; i += 256, j++) { v[j] = __expf(v[j] - mx); sum += v[j]; }
    red[tid] = sum;
    __syncthreads();
    for (int s = 128; s > 0; s >>= 1) {
        if (tid < s) red[tid] += red[tid + s];
        __syncthreads();
    }
    const float inv = 1.0f / red[0];
    for (int i = tid, j = 0; i < n; i += 256, j++) row[i] = v[j] * inv;
}

// ---------------------------------------------------------------------------
// Kernel 4: out = x + P @ V  (Vt is K-major; causal K-limit k < m0+128)
// ---------------------------------------------------------------------------
__global__ __launch_bounds__(256, 2) void av_mma(
    const float* __restrict__ x,
    const float* __restrict__ attn,
    float* __restrict__ out)
{
    __shared__ SmemTiles sm;
    const int tid = threadIdx.x, lid = tid & 31, wid = tid >> 5;
    const int wm = wid & 3, wn = wid >> 2;
    const int b  = blockIdx.z;
    const int m0 = blockIdx.y * BM;
    const int n0 = blockIdx.x * BN;

    float acc[2][8][4];
#pragma unroll
    for (int a = 0; a < 2; a++)
#pragma unroll
        for (int bb = 0; bb < 8; bb++)
#pragma unroll
            for (int r = 0; r < 4; r++) acc[a][bb][r] = 0.f;

    const float* A = attn + (size_t)b * SEQ * SEQ + (size_t)m0 * SEQ;
    const float* B = g_Vt + (size_t)b * DM * SEQ + (size_t)n0 * SEQ;
    mma_mainloop(A, SEQ, B, SEQ, (m0 + BM) / BK, &sm, acc, tid);

#pragma unroll
    for (int mt = 0; mt < 2; mt++) {
        size_t row0 = (size_t)b * SEQ + m0 + wm * 32 + mt * 16 + (lid >> 2);
#pragma unroll
        for (int nt = 0; nt < 8; nt++) {
            int col0 = n0 + wn * 64 + nt * 8 + (lid & 3) * 2;
            size_t o0 = row0 * DM + col0;
            size_t o1 = (row0 + 8) * DM + col0;
            float2 x0 = *reinterpret_cast<const float2*>(x + o0);
            float2 x1 = *reinterpret_cast<const float2*>(x + o1);
            *reinterpret_cast<float2*>(out + o0) =
                make_float2(acc[mt][nt][0] + x0.x, acc[mt][nt][1] + x0.y);
            *reinterpret_cast<float2*>(out + o1) =
                make_float2(acc[mt][nt][2] + x1.x, acc[mt][nt][3] + x1.y);
        }
    }
}

// ---------------------------------------------------------------------------
extern "C" void kernel_launch(void* const* d_in, const int* in_sizes, int n_in,
                              void* d_out, int out_size)
{
    const float* x  = (const float*)d_in[0];
    const float* Wq = (const float*)d_in[1];
    const float* Wk = (const float*)d_in[2];
    const float* Wv = (const float*)d_in[3];

    float* out  = (float*)d_out;                 // [B*S, D]
    float* attn = out + (size_t)MTOT * DM;       // [B, S, S]

    dim3 t(256);
    qkv_mma    <<<dim3(DM/BN,  MTOT/BM, 3),     t>>>(x, Wq, Wk, Wv);
    scores_mma <<<dim3(SEQ/BN, SEQ/BM,  BATCH), t>>>(attn);
    softmax_kernel<<<MTOT, t>>>(attn);
    av_mma     <<<dim3(DM/BN,  SEQ/BM,  BATCH), t>>>(x, attn, out);
}